// round 3
// baseline (speedup 1.0000x reference)
#include <cuda_runtime.h>
#include <cuda_bf16.h>
#include <math.h>
#include <stdint.h>

typedef unsigned long long ULL;
typedef unsigned int u32;

#define H 40
#define W 40
#define CIN 2048
#define CMID 256
#define NPIX 1600
#define NANCH 8000
#define MAXDET 300

__device__ __constant__ float c_anchor[5] = {32.f, 64.f, 128.f, 256.f, 512.f};

// ---------------- device scratch (static; no allocation) ----------------
__device__ float  g_partial[9 * NPIX * CMID];   // per-tap conv partials
__device__ float  g_x[NPIX * CMID];             // conv+bias+relu output
__device__ float  g_scores[NANCH];
__device__ float4 g_boxes[NANCH];
__device__ float  g_rois[MAXDET * 4];

// =====================================================================
// Kernel 1: tap-split implicit GEMM.  grid (25, 2, 9), 128 threads.
// Block tile 64 pixels x 128 couts, per-thread 8x8.
// A is stored in smem PRE-DUPLICATED as {v,v} ULLs so the inner loop is
// pure LDS.128 + fma.rn.f32x2 (no broadcast MOVs).
// =====================================================================
__global__ __launch_bounds__(128) void conv3x3_partial(
    const float* __restrict__ feat, const float* __restrict__ w)
{
    const int mt = blockIdx.x, nt = blockIdx.y, tap = blockIdx.z;
    const int dy = tap / 3 - 1, dx = tap % 3 - 1;
    const int m0 = mt * 64, n0 = nt * 128;
    const int tid = threadIdx.x;

    __shared__ ULL   Asd[16][64];    // [k][pixel], duplicated floats
    __shared__ float Bsf[16][132];   // [k][cout], padded (16B-aligned rows)

    // A loader: 64 px x 16 k per chunk; thread -> (pixel, 8 k)
    const int pl = tid & 63, kh = tid >> 6;
    const int p = m0 + pl;
    const int py = p / W, px = p - py * W;
    const int sy = py + dy, sx = px + dx;
    const bool valid = (sx >= 0) && (sx < W) && (sy >= 0) && (sy < H);
    const float* aptr = feat + ((size_t)(valid ? (sy * W + sx) : 0) * CIN + kh * 8);

    // B loader: 16 k x 128 n per chunk; thread -> (1 k-row, 16 n)
    const int kr = tid >> 3, seg = tid & 7;
    const float* bptr = w + ((size_t)(tap * CIN + kr) * CMID + n0 + seg * 16);

    // compute mapping: 8 m-groups x 16 n-groups
    const int mg = tid >> 4, ng = tid & 15;

    ULL acc[8][4];
#pragma unroll
    for (int i = 0; i < 8; i++)
#pragma unroll
        for (int j = 0; j < 4; j++) acc[i][j] = 0ull;

    for (int c0 = 0; c0 < CIN; c0 += 16) {
        float4 ra0 = make_float4(0.f, 0.f, 0.f, 0.f), ra1 = ra0;
        if (valid) { ra0 = *(const float4*)aptr; ra1 = *(const float4*)(aptr + 4); }
        float4 rb0 = *(const float4*)bptr;
        float4 rb1 = *(const float4*)(bptr + 4);
        float4 rb2 = *(const float4*)(bptr + 8);
        float4 rb3 = *(const float4*)(bptr + 12);
        __syncthreads();
        {
            float av[8] = {ra0.x, ra0.y, ra0.z, ra0.w, ra1.x, ra1.y, ra1.z, ra1.w};
#pragma unroll
            for (int j = 0; j < 8; j++) {
                u32 b = __float_as_uint(av[j]);
                ULL d;
                asm("mov.b64 %0, {%1, %1};" : "=l"(d) : "r"(b));
                Asd[kh * 8 + j][pl] = d;
            }
        }
        *(float4*)&Bsf[kr][seg * 16 + 0]  = rb0;
        *(float4*)&Bsf[kr][seg * 16 + 4]  = rb1;
        *(float4*)&Bsf[kr][seg * 16 + 8]  = rb2;
        *(float4*)&Bsf[kr][seg * 16 + 12] = rb3;
        __syncthreads();
        aptr += 16;
        bptr += (size_t)16 * CMID;

#pragma unroll
        for (int kc = 0; kc < 16; kc++) {
            ulonglong2 a01 = *(const ulonglong2*)&Asd[kc][mg * 8 + 0];
            ulonglong2 a23 = *(const ulonglong2*)&Asd[kc][mg * 8 + 2];
            ulonglong2 a45 = *(const ulonglong2*)&Asd[kc][mg * 8 + 4];
            ulonglong2 a67 = *(const ulonglong2*)&Asd[kc][mg * 8 + 6];
            ulonglong2 b03 = *(const ulonglong2*)&Bsf[kc][ng * 8 + 0];
            ulonglong2 b47 = *(const ulonglong2*)&Bsf[kc][ng * 8 + 4];
            ULL am[8] = {a01.x, a01.y, a23.x, a23.y, a45.x, a45.y, a67.x, a67.y};
            ULL bq[4] = {b03.x, b03.y, b47.x, b47.y};
#pragma unroll
            for (int mm = 0; mm < 8; mm++)
#pragma unroll
                for (int q = 0; q < 4; q++)
                    asm("fma.rn.f32x2 %0, %1, %2, %0;"
                        : "+l"(acc[mm][q]) : "l"(am[mm]), "l"(bq[q]));
        }
    }

    // store partials (each ULL = 2 consecutive fp32 couts)
#pragma unroll
    for (int mm = 0; mm < 8; mm++) {
        int mrow = m0 + mg * 8 + mm;
        size_t base = ((size_t)tap * NPIX + mrow) * CMID + n0 + ng * 8;
        ulonglong2 lo, hi;
        lo.x = acc[mm][0]; lo.y = acc[mm][1];
        hi.x = acc[mm][2]; hi.y = acc[mm][3];
        *(ulonglong2*)&g_partial[base + 0] = lo;
        *(ulonglong2*)&g_partial[base + 4] = hi;
    }
}

// =====================================================================
// Kernel 2: fixed-order tap reduce + bias + relu.  grid 1600, 256 thr.
// =====================================================================
__global__ void reduce_taps(const float* __restrict__ conv_b)
{
    const int m = blockIdx.x, n = threadIdx.x;
    float s = conv_b[n];
#pragma unroll
    for (int t = 0; t < 9; t++)
        s += g_partial[((size_t)t * NPIX + m) * CMID + n];
    g_x[(size_t)m * CMID + n] = fmaxf(s, 0.f);
}

// =====================================================================
// Kernel 3: 1x1 heads + score + anchor decode. grid 1600, 256 thr.
// =====================================================================
__global__ void heads_decode(
    const float* __restrict__ cls_w, const float* __restrict__ cls_b,
    const float* __restrict__ reg_w, const float* __restrict__ reg_b)
{
    const int p = blockIdx.x;
    const int tid = threadIdx.x;
    const int wid = tid >> 5, lid = tid & 31;
    __shared__ float xs[256];
    __shared__ float ob[32];

    xs[tid] = g_x[(size_t)p * CMID + tid];
    __syncthreads();

    for (int o = wid; o < 30; o += 8) {
        const float* wm;
        int ld, col;
        float bias;
        if (o < 10) { wm = cls_w; ld = 10; col = o;      bias = cls_b[o]; }
        else        { wm = reg_w; ld = 20; col = o - 10; bias = reg_b[o - 10]; }
        float s = 0.f;
        for (int k = lid; k < 256; k += 32)
            s += xs[k] * wm[(size_t)k * ld + col];
#pragma unroll
        for (int off = 16; off > 0; off >>= 1)
            s += __shfl_xor_sync(0xFFFFFFFFu, s, off);
        if (lid == 0) ob[o] = s + bias;
    }
    __syncthreads();

    if (tid < 5) {
        const int a = tid;
        float l0 = ob[2 * a], l1 = ob[2 * a + 1];
        float score = 1.f / (1.f + expf(l0 - l1));
        float d0 = ob[10 + 4 * a + 0];
        float d1 = ob[10 + 4 * a + 1];
        float d2 = ob[10 + 4 * a + 2];
        float d3 = ob[10 + 4 * a + 3];
        float px = (float)(p % W), py = (float)(p / W);
        float base = c_anchor[a];
        float bw = expf(d2) * base;
        float bh = expf(d3) * base;
        float xc = px + d0, yc = py + d1;
        g_scores[p * 5 + a] = score;
        g_boxes[p * 5 + a] = make_float4(xc - 0.5f * bw, yc - 0.5f * bh,
                                         xc + 0.5f * bw, yc + 0.5f * bh);
    }
}

// =====================================================================
// Kernel 4: fused stable sort + greedy NMS, fully in shared memory.
// 1 block, 1024 threads, 193.5 KB dynamic smem:
//   [0,64K)       ULL keys[8192]   (score_bits<<32)|(~idx)
//   [64K,189.2K)  float4 boxes[8000] in sorted order
// =====================================================================
__global__ void sort_nms()
{
    extern __shared__ char smraw[];
    ULL* sk = (ULL*)smraw;                       // 8192 keys
    float4* sb = (float4*)(smraw + 65536);       // 8000 sorted boxes

    __shared__ u32 alive[250];
    __shared__ int s_next, s_cur, s_kcnt;
    __shared__ float4 s_box;

    const int tid = threadIdx.x;

    // ---- load keys ----
    for (int i = tid; i < 8192; i += 1024) {
        if (i < NANCH) {
            u32 sbits = __float_as_uint(g_scores[i]);  // (0,1): order-preserving bits
            sk[i] = ((ULL)sbits << 32) | (ULL)(0xFFFFFFFFu - (u32)i);
        } else {
            sk[i] = 0ull;
        }
    }
    __syncthreads();

    // ---- bitonic sort (descending) ----
    for (int k = 2; k <= 8192; k <<= 1) {
        for (int j = k >> 1; j > 0; j >>= 1) {
            for (int t = tid; t < 4096; t += 1024) {
                int i = ((t & ~(j - 1)) << 1) | (t & (j - 1));
                int l = i | j;
                bool desc = ((i & k) == 0);
                ULL a = sk[i], b = sk[l];
                if (desc ? (a < b) : (a > b)) { sk[i] = b; sk[l] = a; }
            }
            __syncthreads();
        }
    }

    // ---- gather boxes into sorted order (smem) ----
    for (int i = tid; i < NANCH; i += 1024) {
        u32 idx = 0xFFFFFFFFu - (u32)(sk[i] & 0xFFFFFFFFull);
        sb[i] = g_boxes[idx];
    }
    if (tid < 250) alive[tid] = 0xFFFFFFFFu;
    if (tid == 0) { s_cur = 0; s_kcnt = 0; }
    __syncthreads();

    // ---- greedy NMS ----
    while (true) {
        if (tid == 0) {
            int nx = -1;
            int sw = s_cur >> 5;
            for (int wd = sw; wd < 250; wd++) {
                u32 m = alive[wd];
                if (wd == sw) m &= ~((s_cur & 31) ? ((1u << (s_cur & 31)) - 1u) : 0u);
                if (m) { nx = wd * 32 + __ffs(m) - 1; break; }
            }
            if (nx >= 0 && s_kcnt < MAXDET) {
                float4 b = sb[nx];
                s_box = b;
                g_rois[s_kcnt * 4 + 0] = b.x;
                g_rois[s_kcnt * 4 + 1] = b.y;
                g_rois[s_kcnt * 4 + 2] = b.z;
                g_rois[s_kcnt * 4 + 3] = b.w;
                s_kcnt++;
                s_cur = nx + 1;
                s_next = nx;
            } else {
                s_next = -1;
            }
        }
        __syncthreads();
        int nx = s_next;
        if (nx < 0) break;

        float4 kb = s_box;
        float areaK = (kb.z - kb.x) * (kb.w - kb.y);

        if (tid < 250) {
            int base = tid * 32;
            u32 mask;
            if (base > nx)            mask = 0xFFFFFFFFu;
            else if (base + 31 <= nx) mask = 0u;
            else                      mask = ~((1u << (nx - base + 1)) - 1u);
            u32 cand = alive[tid] & mask;
            u32 kill = 0;
            while (cand) {
                int b = __ffs(cand) - 1;
                cand &= cand - 1;
                float4 bb = sb[base + b];
                float iw = fminf(kb.z, bb.z) - fmaxf(kb.x, bb.x);
                float ih = fminf(kb.w, bb.w) - fmaxf(kb.y, bb.y);
                iw = fmaxf(iw, 0.f); ih = fmaxf(ih, 0.f);
                float inter = iw * ih;
                float areaB = (bb.z - bb.x) * (bb.w - bb.y);
                float iou = __fdiv_rn(inter, areaK + areaB - inter);
                if (iou >= 0.7f) kill |= (1u << b);
            }
            if (kill) alive[tid] &= ~kill;
        }
        __syncthreads();
    }

    // ---- zero remaining roi rows ----
    int kc = s_kcnt;
    int rem = (MAXDET - kc) * 4;
    for (int e = tid; e < rem; e += 1024) g_rois[kc * 4 + e] = 0.f;
}

// =====================================================================
// Kernel 5: FC head + softmax + output. grid 300, 128 threads.
// out layout: [class_scores 300x4 | box_deltas 300x4 | rois 300x4]
// =====================================================================
__global__ void fc_head(
    const float* __restrict__ fc1_w, const float* __restrict__ fc1_b,
    const float* __restrict__ clsh_w, const float* __restrict__ clsh_b,
    const float* __restrict__ regh_w, const float* __restrict__ regh_b,
    float* __restrict__ out)
{
    const int r = blockIdx.x;
    const int tid = threadIdx.x;
    __shared__ float s_roi[4];
    __shared__ float red[8][128];

    if (tid < 4) s_roi[tid] = g_rois[r * 4 + tid];
    __syncthreads();
    float r0 = s_roi[0], r1 = s_roi[1], r2 = s_roi[2], r3 = s_roi[3];

    float cls[4] = {0.f, 0.f, 0.f, 0.f};
    float reg[4] = {0.f, 0.f, 0.f, 0.f};
    for (int j = tid; j < 1024; j += 128) {
        float fc = r0 * fc1_w[j] + r1 * fc1_w[1024 + j]
                 + r2 * fc1_w[2048 + j] + r3 * fc1_w[3072 + j] + fc1_b[j];
        fc = fmaxf(fc, 0.f);
#pragma unroll
        for (int c = 0; c < 4; c++) {
            cls[c] += fc * clsh_w[j * 4 + c];
            reg[c] += fc * regh_w[j * 4 + c];
        }
    }
#pragma unroll
    for (int c = 0; c < 4; c++) { red[c][tid] = cls[c]; red[4 + c][tid] = reg[c]; }
    __syncthreads();
    for (int s = 64; s > 0; s >>= 1) {
        if (tid < s) {
#pragma unroll
            for (int c = 0; c < 8; c++) red[c][tid] += red[c][tid + s];
        }
        __syncthreads();
    }
    if (tid == 0) {
        float lg[4], mx = -1e30f;
#pragma unroll
        for (int c = 0; c < 4; c++) { lg[c] = red[c][0] + clsh_b[c]; mx = fmaxf(mx, lg[c]); }
        float es[4], sum = 0.f;
#pragma unroll
        for (int c = 0; c < 4; c++) { es[c] = expf(lg[c] - mx); sum += es[c]; }
#pragma unroll
        for (int c = 0; c < 4; c++) {
            out[r * 4 + c]        = es[c] / sum;                 // class_scores
            out[1200 + r * 4 + c] = red[4 + c][0] + regh_b[c];   // box_deltas
            out[2400 + r * 4 + c] = s_roi[c];                    // rois
        }
    }
}

// =====================================================================
extern "C" void kernel_launch(void* const* d_in, const int* in_sizes, int n_in,
                              void* d_out, int out_size)
{
    const float* feat   = (const float*)d_in[0];
    const float* conv_w = (const float*)d_in[1];
    const float* conv_b = (const float*)d_in[2];
    const float* cls_w  = (const float*)d_in[3];
    const float* cls_b  = (const float*)d_in[4];
    const float* reg_w  = (const float*)d_in[5];
    const float* reg_b  = (const float*)d_in[6];
    const float* fc1_w  = (const float*)d_in[7];
    const float* fc1_b  = (const float*)d_in[8];
    const float* clsh_w = (const float*)d_in[9];
    const float* clsh_b = (const float*)d_in[10];
    const float* regh_w = (const float*)d_in[11];
    const float* regh_b = (const float*)d_in[12];
    float* out = (float*)d_out;

    static int smem_set = 0;
    if (!smem_set) {
        cudaFuncSetAttribute(sort_nms, cudaFuncAttributeMaxDynamicSharedMemorySize,
                             65536 + NANCH * 16);
        smem_set = 1;
    }

    conv3x3_partial<<<dim3(25, 2, 9), 128>>>(feat, conv_w);
    reduce_taps<<<NPIX, 256>>>(conv_b);
    heads_decode<<<NPIX, 256>>>(cls_w, cls_b, reg_w, reg_b);
    sort_nms<<<1, 1024, 65536 + NANCH * 16>>>();
    fc_head<<<MAXDET, 128>>>(fc1_w, fc1_b, clsh_w, clsh_b, regh_w, regh_b, out);
}

// round 4
// speedup vs baseline: 1.1520x; 1.1520x over previous
#include <cuda_runtime.h>
#include <cuda_bf16.h>
#include <math.h>
#include <stdint.h>

typedef unsigned long long ULL;
typedef unsigned int u32;

#define H 40
#define W 40
#define CIN 2048
#define CMID 256
#define NPIX 1600
#define NANCH 8000
#define MAXDET 300

__device__ __constant__ float c_anchor[5] = {32.f, 64.f, 128.f, 256.f, 512.f};

// ---------------- device scratch (static; no allocation) ----------------
__device__ float  g_partial[9 * NPIX * CMID];   // per-tap conv partials
__device__ float  g_x[NPIX * CMID];             // conv+bias+relu output
__device__ float  g_scores[NANCH];
__device__ float4 g_boxes[NANCH];
__device__ float  g_rois[MAXDET * 4];

// =====================================================================
// Kernel 1: tap-split implicit GEMM.  grid (25, 2, 9), 128 threads.
// Block tile 64 pixels x 128 couts, per-thread 8x8.
// A stored as plain floats in smem (no duplication); broadcast into
// {v,v} register pairs inside the FMA loop.  Inner loop: 4 LDS.128 +
// 8 packs + 32 fma.rn.f32x2 per kc -> FMA-pipe bound.
// =====================================================================
__global__ __launch_bounds__(128) void conv3x3_partial(
    const float* __restrict__ feat, const float* __restrict__ w)
{
    const int mt = blockIdx.x, nt = blockIdx.y, tap = blockIdx.z;
    const int dy = tap / 3 - 1, dx = tap % 3 - 1;
    const int m0 = mt * 64, n0 = nt * 128;
    const int tid = threadIdx.x;

    __shared__ float Asf[16][68];    // [k][pixel], padded (16B-aligned rows)
    __shared__ float Bsf[16][132];   // [k][cout],  padded (16B-aligned rows)

    // A loader: 64 px x 16 k per chunk; thread -> (pixel, 8 k)
    const int pl = tid & 63, kh = tid >> 6;
    const int p = m0 + pl;
    const int py = p / W, px = p - py * W;
    const int sy = py + dy, sx = px + dx;
    const bool valid = (sx >= 0) && (sx < W) && (sy >= 0) && (sy < H);
    const float* aptr = feat + ((size_t)(valid ? (sy * W + sx) : 0) * CIN + kh * 8);

    // B loader: 16 k x 128 n per chunk; thread -> (1 k-row, 16 n)
    const int kr = tid >> 3, seg = tid & 7;
    const float* bptr = w + ((size_t)(tap * CIN + kr) * CMID + n0 + seg * 16);

    // compute mapping: 8 m-groups x 16 n-groups
    const int mg = tid >> 4, ng = tid & 15;

    ULL acc[8][4];
#pragma unroll
    for (int i = 0; i < 8; i++)
#pragma unroll
        for (int j = 0; j < 4; j++) acc[i][j] = 0ull;

    for (int c0 = 0; c0 < CIN; c0 += 16) {
        float4 ra0 = make_float4(0.f, 0.f, 0.f, 0.f), ra1 = ra0;
        if (valid) { ra0 = *(const float4*)aptr; ra1 = *(const float4*)(aptr + 4); }
        float4 rb0 = *(const float4*)bptr;
        float4 rb1 = *(const float4*)(bptr + 4);
        float4 rb2 = *(const float4*)(bptr + 8);
        float4 rb3 = *(const float4*)(bptr + 12);
        __syncthreads();
        {
            float av[8] = {ra0.x, ra0.y, ra0.z, ra0.w, ra1.x, ra1.y, ra1.z, ra1.w};
#pragma unroll
            for (int j = 0; j < 8; j++) Asf[kh * 8 + j][pl] = av[j];
        }
        *(float4*)&Bsf[kr][seg * 16 + 0]  = rb0;
        *(float4*)&Bsf[kr][seg * 16 + 4]  = rb1;
        *(float4*)&Bsf[kr][seg * 16 + 8]  = rb2;
        *(float4*)&Bsf[kr][seg * 16 + 12] = rb3;
        __syncthreads();
        aptr += 16;
        bptr += (size_t)16 * CMID;

#pragma unroll
        for (int kc = 0; kc < 16; kc++) {
            float4 a0 = *(const float4*)&Asf[kc][mg * 8 + 0];
            float4 a1 = *(const float4*)&Asf[kc][mg * 8 + 4];
            ulonglong2 b03 = *(const ulonglong2*)&Bsf[kc][ng * 8 + 0];
            ulonglong2 b47 = *(const ulonglong2*)&Bsf[kc][ng * 8 + 4];
            ULL bq[4] = {b03.x, b03.y, b47.x, b47.y};
            float am[8] = {a0.x, a0.y, a0.z, a0.w, a1.x, a1.y, a1.z, a1.w};
#pragma unroll
            for (int mm = 0; mm < 8; mm++) {
                u32 au = __float_as_uint(am[mm]);
                ULL a2;
                asm("mov.b64 %0, {%1, %1};" : "=l"(a2) : "r"(au));
#pragma unroll
                for (int q = 0; q < 4; q++)
                    asm("fma.rn.f32x2 %0, %1, %2, %0;"
                        : "+l"(acc[mm][q]) : "l"(a2), "l"(bq[q]));
            }
        }
    }

    // store partials (each ULL = 2 consecutive fp32 couts)
#pragma unroll
    for (int mm = 0; mm < 8; mm++) {
        int mrow = m0 + mg * 8 + mm;
        size_t base = ((size_t)tap * NPIX + mrow) * CMID + n0 + ng * 8;
        ulonglong2 lo, hi;
        lo.x = acc[mm][0]; lo.y = acc[mm][1];
        hi.x = acc[mm][2]; hi.y = acc[mm][3];
        *(ulonglong2*)&g_partial[base + 0] = lo;
        *(ulonglong2*)&g_partial[base + 4] = hi;
    }
}

// =====================================================================
// Kernel 2: fixed-order tap reduce + bias + relu.  grid 1600, 256 thr.
// =====================================================================
__global__ void reduce_taps(const float* __restrict__ conv_b)
{
    const int m = blockIdx.x, n = threadIdx.x;
    float s = conv_b[n];
#pragma unroll
    for (int t = 0; t < 9; t++)
        s += g_partial[((size_t)t * NPIX + m) * CMID + n];
    g_x[(size_t)m * CMID + n] = fmaxf(s, 0.f);
}

// =====================================================================
// Kernel 3: 1x1 heads + score + anchor decode. grid 1600, 256 thr.
// =====================================================================
__global__ void heads_decode(
    const float* __restrict__ cls_w, const float* __restrict__ cls_b,
    const float* __restrict__ reg_w, const float* __restrict__ reg_b)
{
    const int p = blockIdx.x;
    const int tid = threadIdx.x;
    const int wid = tid >> 5, lid = tid & 31;
    __shared__ float xs[256];
    __shared__ float ob[32];

    xs[tid] = g_x[(size_t)p * CMID + tid];
    __syncthreads();

    for (int o = wid; o < 30; o += 8) {
        const float* wm;
        int ld, col;
        float bias;
        if (o < 10) { wm = cls_w; ld = 10; col = o;      bias = cls_b[o]; }
        else        { wm = reg_w; ld = 20; col = o - 10; bias = reg_b[o - 10]; }
        float s = 0.f;
        for (int k = lid; k < 256; k += 32)
            s += xs[k] * wm[(size_t)k * ld + col];
#pragma unroll
        for (int off = 16; off > 0; off >>= 1)
            s += __shfl_xor_sync(0xFFFFFFFFu, s, off);
        if (lid == 0) ob[o] = s + bias;
    }
    __syncthreads();

    if (tid < 5) {
        const int a = tid;
        float l0 = ob[2 * a], l1 = ob[2 * a + 1];
        float score = 1.f / (1.f + expf(l0 - l1));
        float d0 = ob[10 + 4 * a + 0];
        float d1 = ob[10 + 4 * a + 1];
        float d2 = ob[10 + 4 * a + 2];
        float d3 = ob[10 + 4 * a + 3];
        float px = (float)(p % W), py = (float)(p / W);
        float base = c_anchor[a];
        float bw = expf(d2) * base;
        float bh = expf(d3) * base;
        float xc = px + d0, yc = py + d1;
        g_scores[p * 5 + a] = score;
        g_boxes[p * 5 + a] = make_float4(xc - 0.5f * bw, yc - 0.5f * bh,
                                         xc + 0.5f * bw, yc + 0.5f * bh);
    }
}

// =====================================================================
// Kernel 4: fused stable sort + PARALLEL greedy NMS in shared memory.
// 1 block, 1024 threads.
// Suppression pass: all 1024 threads, 8 candidates each (independent
// IoU chains -> ILP); kill bits gathered per 32-box word via ballot
// (warp w of pass p owns word p*32+w -> race-free).
// =====================================================================
__global__ void sort_nms()
{
    extern __shared__ char smraw[];
    ULL* sk = (ULL*)smraw;                       // 8192 keys (64KB)
    float4* sb = (float4*)(smraw + 65536);       // 8000 sorted boxes (125KB)

    __shared__ u32 alive[250];
    __shared__ int s_next, s_cur, s_kcnt;
    __shared__ float4 s_box;

    const int tid = threadIdx.x;

    // ---- load keys: (score_bits<<32)|(~idx): desc score, asc index ----
    for (int i = tid; i < 8192; i += 1024) {
        if (i < NANCH) {
            u32 sbits = __float_as_uint(g_scores[i]);  // (0,1): order-preserving bits
            sk[i] = ((ULL)sbits << 32) | (ULL)(0xFFFFFFFFu - (u32)i);
        } else {
            sk[i] = 0ull;
        }
    }
    __syncthreads();

    // ---- bitonic sort (descending), 4 slots per thread ----
    for (int k = 2; k <= 8192; k <<= 1) {
        for (int j = k >> 1; j > 0; j >>= 1) {
#pragma unroll
            for (int u = 0; u < 4; u++) {
                int t = u * 1024 + tid;
                int i = ((t & ~(j - 1)) << 1) | (t & (j - 1));
                int l = i | j;
                bool desc = ((i & k) == 0);
                ULL a = sk[i], b = sk[l];
                if (desc ? (a < b) : (a > b)) { sk[i] = b; sk[l] = a; }
            }
            __syncthreads();
        }
    }

    // ---- gather boxes into sorted order (smem) ----
    for (int i = tid; i < NANCH; i += 1024) {
        u32 idx = 0xFFFFFFFFu - (u32)(sk[i] & 0xFFFFFFFFull);
        sb[i] = g_boxes[idx];
    }
    if (tid < 250) alive[tid] = 0xFFFFFFFFu;
    if (tid == 0) { s_cur = 0; s_kcnt = 0; }
    __syncthreads();

    // ---- greedy NMS ----
    const int lane = tid & 31;
    const int wrp  = tid >> 5;
    while (true) {
        if (tid == 0) {
            int nx = -1;
            int sw = s_cur >> 5;
            for (int wd = sw; wd < 250; wd++) {
                u32 m = alive[wd];
                if (wd == sw) m &= ~((s_cur & 31) ? ((1u << (s_cur & 31)) - 1u) : 0u);
                if (m) { nx = wd * 32 + __ffs(m) - 1; break; }
            }
            if (nx >= 0 && s_kcnt < MAXDET) {
                float4 b = sb[nx];
                s_box = b;
                g_rois[s_kcnt * 4 + 0] = b.x;
                g_rois[s_kcnt * 4 + 1] = b.y;
                g_rois[s_kcnt * 4 + 2] = b.z;
                g_rois[s_kcnt * 4 + 3] = b.w;
                s_kcnt++;
                s_cur = nx + 1;
                s_next = nx;
            } else {
                s_next = -1;
            }
        }
        __syncthreads();
        const int nx = s_next;
        if (nx < 0) break;

        const float4 kb = s_box;
        const float areaK = (kb.z - kb.x) * (kb.w - kb.y);

#pragma unroll
        for (int pass = 0; pass < 8; pass++) {
            const int i = pass * 1024 + tid;
            bool kill = false;
            if (i < NANCH && i > nx) {
                const int wd = i >> 5;
                if (alive[wd] & (1u << (i & 31))) {
                    float4 bb = sb[i];
                    float iw = fminf(kb.z, bb.z) - fmaxf(kb.x, bb.x);
                    float ih = fminf(kb.w, bb.w) - fmaxf(kb.y, bb.y);
                    iw = fmaxf(iw, 0.f); ih = fmaxf(ih, 0.f);
                    float inter = iw * ih;
                    float areaB = (bb.z - bb.x) * (bb.w - bb.y);
                    float iou = __fdiv_rn(inter, areaK + areaB - inter);
                    kill = (iou >= 0.7f);
                }
            }
            u32 km = __ballot_sync(0xFFFFFFFFu, kill);
            if (lane == 0 && km) {
                int wd = pass * 32 + wrp;       // == (pass*1024+tid)>>5
                if (wd < 250) alive[wd] &= ~km;
            }
        }
        __syncthreads();
    }

    // ---- zero remaining roi rows ----
    int kc = s_kcnt;
    int rem = (MAXDET - kc) * 4;
    for (int e = tid; e < rem; e += 1024) g_rois[kc * 4 + e] = 0.f;
}

// =====================================================================
// Kernel 5: FC head + softmax + output. grid 300, 128 threads.
// out layout: [class_scores 300x4 | box_deltas 300x4 | rois 300x4]
// =====================================================================
__global__ void fc_head(
    const float* __restrict__ fc1_w, const float* __restrict__ fc1_b,
    const float* __restrict__ clsh_w, const float* __restrict__ clsh_b,
    const float* __restrict__ regh_w, const float* __restrict__ regh_b,
    float* __restrict__ out)
{
    const int r = blockIdx.x;
    const int tid = threadIdx.x;
    __shared__ float s_roi[4];
    __shared__ float red[8][128];

    if (tid < 4) s_roi[tid] = g_rois[r * 4 + tid];
    __syncthreads();
    float r0 = s_roi[0], r1 = s_roi[1], r2 = s_roi[2], r3 = s_roi[3];

    float cls[4] = {0.f, 0.f, 0.f, 0.f};
    float reg[4] = {0.f, 0.f, 0.f, 0.f};
    for (int j = tid; j < 1024; j += 128) {
        float fc = r0 * fc1_w[j] + r1 * fc1_w[1024 + j]
                 + r2 * fc1_w[2048 + j] + r3 * fc1_w[3072 + j] + fc1_b[j];
        fc = fmaxf(fc, 0.f);
#pragma unroll
        for (int c = 0; c < 4; c++) {
            cls[c] += fc * clsh_w[j * 4 + c];
            reg[c] += fc * regh_w[j * 4 + c];
        }
    }
#pragma unroll
    for (int c = 0; c < 4; c++) { red[c][tid] = cls[c]; red[4 + c][tid] = reg[c]; }
    __syncthreads();
    for (int s = 64; s > 0; s >>= 1) {
        if (tid < s) {
#pragma unroll
            for (int c = 0; c < 8; c++) red[c][tid] += red[c][tid + s];
        }
        __syncthreads();
    }
    if (tid == 0) {
        float lg[4], mx = -1e30f;
#pragma unroll
        for (int c = 0; c < 4; c++) { lg[c] = red[c][0] + clsh_b[c]; mx = fmaxf(mx, lg[c]); }
        float es[4], sum = 0.f;
#pragma unroll
        for (int c = 0; c < 4; c++) { es[c] = expf(lg[c] - mx); sum += es[c]; }
#pragma unroll
        for (int c = 0; c < 4; c++) {
            out[r * 4 + c]        = es[c] / sum;                 // class_scores
            out[1200 + r * 4 + c] = red[4 + c][0] + regh_b[c];   // box_deltas
            out[2400 + r * 4 + c] = s_roi[c];                    // rois
        }
    }
}

// =====================================================================
extern "C" void kernel_launch(void* const* d_in, const int* in_sizes, int n_in,
                              void* d_out, int out_size)
{
    const float* feat   = (const float*)d_in[0];
    const float* conv_w = (const float*)d_in[1];
    const float* conv_b = (const float*)d_in[2];
    const float* cls_w  = (const float*)d_in[3];
    const float* cls_b  = (const float*)d_in[4];
    const float* reg_w  = (const float*)d_in[5];
    const float* reg_b  = (const float*)d_in[6];
    const float* fc1_w  = (const float*)d_in[7];
    const float* fc1_b  = (const float*)d_in[8];
    const float* clsh_w = (const float*)d_in[9];
    const float* clsh_b = (const float*)d_in[10];
    const float* regh_w = (const float*)d_in[11];
    const float* regh_b = (const float*)d_in[12];
    float* out = (float*)d_out;

    static int smem_set = 0;
    if (!smem_set) {
        cudaFuncSetAttribute(sort_nms, cudaFuncAttributeMaxDynamicSharedMemorySize,
                             65536 + NANCH * 16);
        smem_set = 1;
    }

    conv3x3_partial<<<dim3(25, 2, 9), 128>>>(feat, conv_w);
    reduce_taps<<<NPIX, 256>>>(conv_b);
    heads_decode<<<NPIX, 256>>>(cls_w, cls_b, reg_w, reg_b);
    sort_nms<<<1, 1024, 65536 + NANCH * 16>>>();
    fc_head<<<MAXDET, 128>>>(fc1_w, fc1_b, clsh_w, clsh_b, regh_w, regh_b, out);
}

// round 5
// speedup vs baseline: 1.6115x; 1.3988x over previous
#include <cuda_runtime.h>
#include <cuda_bf16.h>
#include <math.h>
#include <stdint.h>

typedef unsigned long long ULL;
typedef unsigned int u32;

#define H 40
#define W 40
#define CIN 2048
#define CMID 256
#define NPIX 1600
#define NANCH 8000
#define MAXDET 300
#define NWORDS 250          // 8000/32

__device__ __constant__ float c_anchor[5] = {32.f, 64.f, 128.f, 256.f, 512.f};

// ---------------- device scratch (static; no allocation) ----------------
__device__ float  g_partial[9 * NPIX * CMID];   // per-tap conv partials
__device__ float  g_x[NPIX * CMID];             // conv+bias+relu output
__device__ float  g_scores[NANCH];
__device__ float4 g_boxes[NANCH];
__device__ float4 g_boxes_sorted[NANCH];
__device__ u32    g_mask[NANCH * NWORDS];       // suppression bitmap rows (8MB)
__device__ float  g_rois[MAXDET * 4];

// =====================================================================
// Kernel 1: tap-split implicit GEMM.  grid (25, 2, 9), 128 threads.
// Block tile 64 pixels x 128 couts, per-thread 8x8, fma.rn.f32x2.
// =====================================================================
__global__ __launch_bounds__(128) void conv3x3_partial(
    const float* __restrict__ feat, const float* __restrict__ w)
{
    const int mt = blockIdx.x, nt = blockIdx.y, tap = blockIdx.z;
    const int dy = tap / 3 - 1, dx = tap % 3 - 1;
    const int m0 = mt * 64, n0 = nt * 128;
    const int tid = threadIdx.x;

    __shared__ float Asf[16][68];
    __shared__ float Bsf[16][132];

    const int pl = tid & 63, kh = tid >> 6;
    const int p = m0 + pl;
    const int py = p / W, px = p - py * W;
    const int sy = py + dy, sx = px + dx;
    const bool valid = (sx >= 0) && (sx < W) && (sy >= 0) && (sy < H);
    const float* aptr = feat + ((size_t)(valid ? (sy * W + sx) : 0) * CIN + kh * 8);

    const int kr = tid >> 3, seg = tid & 7;
    const float* bptr = w + ((size_t)(tap * CIN + kr) * CMID + n0 + seg * 16);

    const int mg = tid >> 4, ng = tid & 15;

    ULL acc[8][4];
#pragma unroll
    for (int i = 0; i < 8; i++)
#pragma unroll
        for (int j = 0; j < 4; j++) acc[i][j] = 0ull;

    for (int c0 = 0; c0 < CIN; c0 += 16) {
        float4 ra0 = make_float4(0.f, 0.f, 0.f, 0.f), ra1 = ra0;
        if (valid) { ra0 = *(const float4*)aptr; ra1 = *(const float4*)(aptr + 4); }
        float4 rb0 = *(const float4*)bptr;
        float4 rb1 = *(const float4*)(bptr + 4);
        float4 rb2 = *(const float4*)(bptr + 8);
        float4 rb3 = *(const float4*)(bptr + 12);
        __syncthreads();
        {
            float av[8] = {ra0.x, ra0.y, ra0.z, ra0.w, ra1.x, ra1.y, ra1.z, ra1.w};
#pragma unroll
            for (int j = 0; j < 8; j++) Asf[kh * 8 + j][pl] = av[j];
        }
        *(float4*)&Bsf[kr][seg * 16 + 0]  = rb0;
        *(float4*)&Bsf[kr][seg * 16 + 4]  = rb1;
        *(float4*)&Bsf[kr][seg * 16 + 8]  = rb2;
        *(float4*)&Bsf[kr][seg * 16 + 12] = rb3;
        __syncthreads();
        aptr += 16;
        bptr += (size_t)16 * CMID;

#pragma unroll
        for (int kc = 0; kc < 16; kc++) {
            float4 a0 = *(const float4*)&Asf[kc][mg * 8 + 0];
            float4 a1 = *(const float4*)&Asf[kc][mg * 8 + 4];
            ulonglong2 b03 = *(const ulonglong2*)&Bsf[kc][ng * 8 + 0];
            ulonglong2 b47 = *(const ulonglong2*)&Bsf[kc][ng * 8 + 4];
            ULL bq[4] = {b03.x, b03.y, b47.x, b47.y};
            float am[8] = {a0.x, a0.y, a0.z, a0.w, a1.x, a1.y, a1.z, a1.w};
#pragma unroll
            for (int mm = 0; mm < 8; mm++) {
                u32 au = __float_as_uint(am[mm]);
                ULL a2;
                asm("mov.b64 %0, {%1, %1};" : "=l"(a2) : "r"(au));
#pragma unroll
                for (int q = 0; q < 4; q++)
                    asm("fma.rn.f32x2 %0, %1, %2, %0;"
                        : "+l"(acc[mm][q]) : "l"(a2), "l"(bq[q]));
            }
        }
    }

#pragma unroll
    for (int mm = 0; mm < 8; mm++) {
        int mrow = m0 + mg * 8 + mm;
        size_t base = ((size_t)tap * NPIX + mrow) * CMID + n0 + ng * 8;
        ulonglong2 lo, hi;
        lo.x = acc[mm][0]; lo.y = acc[mm][1];
        hi.x = acc[mm][2]; hi.y = acc[mm][3];
        *(ulonglong2*)&g_partial[base + 0] = lo;
        *(ulonglong2*)&g_partial[base + 4] = hi;
    }
}

// =====================================================================
// Kernel 2: fixed-order tap reduce + bias + relu.  grid 1600, 256 thr.
// =====================================================================
__global__ void reduce_taps(const float* __restrict__ conv_b)
{
    const int m = blockIdx.x, n = threadIdx.x;
    float s = conv_b[n];
#pragma unroll
    for (int t = 0; t < 9; t++)
        s += g_partial[((size_t)t * NPIX + m) * CMID + n];
    g_x[(size_t)m * CMID + n] = fmaxf(s, 0.f);
}

// =====================================================================
// Kernel 3: 1x1 heads + score + anchor decode. grid 1600, 256 thr.
// =====================================================================
__global__ void heads_decode(
    const float* __restrict__ cls_w, const float* __restrict__ cls_b,
    const float* __restrict__ reg_w, const float* __restrict__ reg_b)
{
    const int p = blockIdx.x;
    const int tid = threadIdx.x;
    const int wid = tid >> 5, lid = tid & 31;
    __shared__ float xs[256];
    __shared__ float ob[32];

    xs[tid] = g_x[(size_t)p * CMID + tid];
    __syncthreads();

    for (int o = wid; o < 30; o += 8) {
        const float* wm;
        int ld, col;
        float bias;
        if (o < 10) { wm = cls_w; ld = 10; col = o;      bias = cls_b[o]; }
        else        { wm = reg_w; ld = 20; col = o - 10; bias = reg_b[o - 10]; }
        float s = 0.f;
        for (int k = lid; k < 256; k += 32)
            s += xs[k] * wm[(size_t)k * ld + col];
#pragma unroll
        for (int off = 16; off > 0; off >>= 1)
            s += __shfl_xor_sync(0xFFFFFFFFu, s, off);
        if (lid == 0) ob[o] = s + bias;
    }
    __syncthreads();

    if (tid < 5) {
        const int a = tid;
        float l0 = ob[2 * a], l1 = ob[2 * a + 1];
        float score = 1.f / (1.f + expf(l0 - l1));
        float d0 = ob[10 + 4 * a + 0];
        float d1 = ob[10 + 4 * a + 1];
        float d2 = ob[10 + 4 * a + 2];
        float d3 = ob[10 + 4 * a + 3];
        float px = (float)(p % W), py = (float)(p / W);
        float base = c_anchor[a];
        float bw = expf(d2) * base;
        float bh = expf(d3) * base;
        float xc = px + d0, yc = py + d1;
        g_scores[p * 5 + a] = score;
        g_boxes[p * 5 + a] = make_float4(xc - 0.5f * bw, yc - 0.5f * bh,
                                         xc + 0.5f * bw, yc + 0.5f * bh);
    }
}

// =====================================================================
// Kernel 4: stable descending bitonic sort (1 block, 1024 thr, 64KB),
// then gather boxes into sorted order (gmem).
// key = (score_bits<<32) | (~idx): desc score, asc index.
// =====================================================================
__global__ void sort_kernel()
{
    extern __shared__ ULL sk[];
    const int tid = threadIdx.x;

    for (int i = tid; i < 8192; i += 1024) {
        if (i < NANCH) {
            u32 sbits = __float_as_uint(g_scores[i]);   // (0,1): order-preserving bits
            sk[i] = ((ULL)sbits << 32) | (ULL)(0xFFFFFFFFu - (u32)i);
        } else {
            sk[i] = 0ull;
        }
    }
    __syncthreads();

    for (int k = 2; k <= 8192; k <<= 1) {
        for (int j = k >> 1; j > 0; j >>= 1) {
#pragma unroll
            for (int u = 0; u < 4; u++) {
                int t = u * 1024 + tid;
                int i = ((t & ~(j - 1)) << 1) | (t & (j - 1));
                int l = i | j;
                bool desc = ((i & k) == 0);
                ULL a = sk[i], b = sk[l];
                if (desc ? (a < b) : (a > b)) { sk[i] = b; sk[l] = a; }
            }
            __syncthreads();
        }
    }

    for (int i = tid; i < NANCH; i += 1024) {
        u32 idx = 0xFFFFFFFFu - (u32)(sk[i] & 0xFFFFFFFFull);
        g_boxes_sorted[i] = g_boxes[idx];
    }
}

// =====================================================================
// Kernel 5: pairwise suppression mask, FULLY PARALLEL.
// grid (125 col-chunks, 125 row-chunks), 128 threads.
// Block (bx,by): rows [by*64,+64) x cols [bx*64,+64).
// Thread t: row i_loc=t>>1, word wsel=t&1 (32 cols) -> one u32 of bits.
// bit j set iff (j>i) && (IoU(i,j) >= 0.7), decided by fmaf sign test
// with exact __fdiv_rn fallback inside a +-1e-5 relative band.
// Lower-triangle blocks just zero their words.
// =====================================================================
__global__ __launch_bounds__(128) void mask_build()
{
    const int bx = blockIdx.x, by = blockIdx.y;
    const int tid = threadIdx.x;
    const int i_loc = tid >> 1, wsel = tid & 1;
    const int ig = by * 64 + i_loc;

    if (bx < by) {                       // all j < i here -> zero
        g_mask[(size_t)ig * NWORDS + bx * 2 + wsel] = 0u;
        return;
    }

    __shared__ float4 rb[64]; __shared__ float ra[64];
    __shared__ float4 cb[64]; __shared__ float ca[64];
    if (tid < 64) {
        float4 b = g_boxes_sorted[by * 64 + tid];
        rb[tid] = b; ra[tid] = (b.z - b.x) * (b.w - b.y);
    } else {
        int t = tid - 64;
        float4 b = g_boxes_sorted[bx * 64 + t];
        cb[t] = b; ca[t] = (b.z - b.x) * (b.w - b.y);
    }
    __syncthreads();

    const float4 kb = rb[i_loc];
    const float areaK = ra[i_loc];
    u32 bits = 0;

#pragma unroll 4
    for (int jl = wsel * 32; jl < wsel * 32 + 32; jl++) {
        int jg = bx * 64 + jl;
        if (jg <= ig) continue;
        float4 bb = cb[jl];
        float iw = fminf(kb.z, bb.z) - fmaxf(kb.x, bb.x);
        float ih = fminf(kb.w, bb.w) - fmaxf(kb.y, bb.y);
        if (iw > 0.f && ih > 0.f) {
            float inter = iw * ih;
            float uni = areaK + ca[jl] - inter;
            float d = __fmaf_rn(-0.7f, uni, inter);
            bool kill;
            if (fabsf(d) >= 1e-5f * uni) {
                kill = (d >= 0.f);
            } else {
                kill = (__fdiv_rn(inter, uni) >= 0.7f);   // exact, rare
            }
            if (kill) bits |= (1u << (jl & 31));
        }
    }
    g_mask[(size_t)ig * NWORDS + bx * 2 + wsel] = bits;
}

// =====================================================================
// Kernel 6: serial scan over sorted boxes using mask rows.
// 1 block, 256 threads. remv = suppression bitmap (smem).
// =====================================================================
__global__ void nms_scan()
{
    __shared__ u32 remv[NWORDS];
    __shared__ int s_next, s_k;
    const int tid = threadIdx.x;

    if (tid < NWORDS) remv[tid] = 0u;
    __syncthreads();

    int cur = 0, kcnt = 0;      // live only in thread 0
    while (true) {
        if (tid == 0) {
            int nx = -1;
            int w = cur >> 5;
            u32 off = cur & 31;
            u32 m = (w < NWORDS) ? ((~remv[w]) & (off ? ~((1u << off) - 1u) : 0xFFFFFFFFu)) : 0u;
            while (true) {
                if (m) { nx = (w << 5) + __ffs(m) - 1; break; }
                if (++w >= NWORDS) break;
                m = ~remv[w];
            }
            if (nx >= 0 && kcnt < MAXDET) {
                float4 b = g_boxes_sorted[nx];
                g_rois[kcnt * 4 + 0] = b.x;
                g_rois[kcnt * 4 + 1] = b.y;
                g_rois[kcnt * 4 + 2] = b.z;
                g_rois[kcnt * 4 + 3] = b.w;
                kcnt++;
                cur = nx + 1;
                s_next = nx;
            } else {
                s_next = -1;
            }
        }
        __syncthreads();
        int nx = s_next;
        if (nx < 0) break;
        if (tid < NWORDS) remv[tid] |= g_mask[(size_t)nx * NWORDS + tid];
        __syncthreads();
    }

    if (tid == 0) s_k = kcnt;
    __syncthreads();
    int kc = s_k;
    int rem = (MAXDET - kc) * 4;
    for (int e = tid; e < rem; e += 256) g_rois[kc * 4 + e] = 0.f;
}

// =====================================================================
// Kernel 7: FC head + softmax + output. grid 300, 128 threads.
// out layout: [class_scores 300x4 | box_deltas 300x4 | rois 300x4]
// =====================================================================
__global__ void fc_head(
    const float* __restrict__ fc1_w, const float* __restrict__ fc1_b,
    const float* __restrict__ clsh_w, const float* __restrict__ clsh_b,
    const float* __restrict__ regh_w, const float* __restrict__ regh_b,
    float* __restrict__ out)
{
    const int r = blockIdx.x;
    const int tid = threadIdx.x;
    __shared__ float s_roi[4];
    __shared__ float red[8][128];

    if (tid < 4) s_roi[tid] = g_rois[r * 4 + tid];
    __syncthreads();
    float r0 = s_roi[0], r1 = s_roi[1], r2 = s_roi[2], r3 = s_roi[3];

    float cls[4] = {0.f, 0.f, 0.f, 0.f};
    float reg[4] = {0.f, 0.f, 0.f, 0.f};
    for (int j = tid; j < 1024; j += 128) {
        float fc = r0 * fc1_w[j] + r1 * fc1_w[1024 + j]
                 + r2 * fc1_w[2048 + j] + r3 * fc1_w[3072 + j] + fc1_b[j];
        fc = fmaxf(fc, 0.f);
#pragma unroll
        for (int c = 0; c < 4; c++) {
            cls[c] += fc * clsh_w[j * 4 + c];
            reg[c] += fc * regh_w[j * 4 + c];
        }
    }
#pragma unroll
    for (int c = 0; c < 4; c++) { red[c][tid] = cls[c]; red[4 + c][tid] = reg[c]; }
    __syncthreads();
    for (int s = 64; s > 0; s >>= 1) {
        if (tid < s) {
#pragma unroll
            for (int c = 0; c < 8; c++) red[c][tid] += red[c][tid + s];
        }
        __syncthreads();
    }
    if (tid == 0) {
        float lg[4], mx = -1e30f;
#pragma unroll
        for (int c = 0; c < 4; c++) { lg[c] = red[c][0] + clsh_b[c]; mx = fmaxf(mx, lg[c]); }
        float es[4], sum = 0.f;
#pragma unroll
        for (int c = 0; c < 4; c++) { es[c] = expf(lg[c] - mx); sum += es[c]; }
#pragma unroll
        for (int c = 0; c < 4; c++) {
            out[r * 4 + c]        = es[c] / sum;                 // class_scores
            out[1200 + r * 4 + c] = red[4 + c][0] + regh_b[c];   // box_deltas
            out[2400 + r * 4 + c] = s_roi[c];                    // rois
        }
    }
}

// =====================================================================
extern "C" void kernel_launch(void* const* d_in, const int* in_sizes, int n_in,
                              void* d_out, int out_size)
{
    const float* feat   = (const float*)d_in[0];
    const float* conv_w = (const float*)d_in[1];
    const float* conv_b = (const float*)d_in[2];
    const float* cls_w  = (const float*)d_in[3];
    const float* cls_b  = (const float*)d_in[4];
    const float* reg_w  = (const float*)d_in[5];
    const float* reg_b  = (const float*)d_in[6];
    const float* fc1_w  = (const float*)d_in[7];
    const float* fc1_b  = (const float*)d_in[8];
    const float* clsh_w = (const float*)d_in[9];
    const float* clsh_b = (const float*)d_in[10];
    const float* regh_w = (const float*)d_in[11];
    const float* regh_b = (const float*)d_in[12];
    float* out = (float*)d_out;

    static int smem_set = 0;
    if (!smem_set) {
        cudaFuncSetAttribute(sort_kernel, cudaFuncAttributeMaxDynamicSharedMemorySize, 65536);
        smem_set = 1;
    }

    conv3x3_partial<<<dim3(25, 2, 9), 128>>>(feat, conv_w);
    reduce_taps<<<NPIX, 256>>>(conv_b);
    heads_decode<<<NPIX, 256>>>(cls_w, cls_b, reg_w, reg_b);
    sort_kernel<<<1, 1024, 65536>>>();
    mask_build<<<dim3(125, 125), 128>>>();
    nms_scan<<<1, 256>>>();
    fc_head<<<MAXDET, 128>>>(fc1_w, fc1_b, clsh_w, clsh_b, regh_w, regh_b, out);
}